// round 10
// baseline (speedup 1.0000x reference)
#include <cuda_runtime.h>
#include <math_constants.h>

// ---------------------------------------------------------------------------
// NeuralSpectralBlock2D  (B=16, C=64, H=W=240, P=3, HEAD=8, dh=8, T=4, M=12)
// Tensor-core rewrite: per CTA (8 patches) one tf32 GEMM
//   Y[160 x 72] = W[160 x 64] * X[64 x 72]   via mma.sync.m16n8k8
// rows 0-31 = folded scores1, 32-95 = v, 96-159 = xq (biases added at store).
// Epilogue (softmax/attn1@v/spectral/attn2) = R6 code reading Y from smem.
// Y overlays the dead W region. Residual re-read from global x.
// ---------------------------------------------------------------------------

#define Bn    16
#define Cn    64
#define Hn    240
#define Wn    240
#define NP    8           // patches per CTA
#define NT    256         // 8 warps

#define HPn   80
#define WPn   80
#define WBLK  (WPn / NP)          // 10
#define GRID  (Bn * HPn * WBLK)   // 12800

#define SW 164            // W^T smem stride  [64 k][164]
#define SX 68             // X smem stride    [72 n][68]
#define SY 73             // Y smem stride    [160 m][73]

#define W_F   (64 * SW)           // 10496 floats
#define Y_F   (160 * SY)          // 11680 floats
#define WY_F  11680               // max(W_F, Y_F)
#define X_F   (72 * SX)           // 4896

// small consts
#define S_B   0                   // biasAll[160]
#define S_WT  160                 // wt[m'][c] 1536
#define S_Q   1696                // q[hd][t]  256
#define S_SZ  1952

#define OFF_X   WY_F
#define OFF_SS  (OFF_X + X_F)
#define OFF_PB  (OFF_SS + S_SZ)   // per-patch at/lp buffers (8 x 320)
#define SMEM_F  (OFF_PB + NP * 320)   // 21088 floats
#define SMEM_B  (SMEM_F * 4)          // 84352 bytes -> 2 CTAs/SM

__device__ __align__(16) float g_W[W_F];
__device__ __align__(16) float g_small[S_SZ];

__device__ __forceinline__ float to_tf32(float v) {
    unsigned o;
    asm("cvt.rna.tf32.f32 %0, %1;" : "=r"(o) : "f"(v));
    return __uint_as_float(o);
}

__device__ __forceinline__ void mma_tf32(float c[4],
                                         unsigned a0, unsigned a1,
                                         unsigned a2, unsigned a3,
                                         unsigned b0, unsigned b1) {
    asm volatile(
        "mma.sync.aligned.m16n8k8.row.col.f32.tf32.tf32.f32 "
        "{%0,%1,%2,%3}, {%4,%5,%6,%7}, {%8,%9}, {%0,%1,%2,%3};\n"
        : "+f"(c[0]), "+f"(c[1]), "+f"(c[2]), "+f"(c[3])
        : "r"(a0), "r"(a1), "r"(a2), "r"(a3), "r"(b0), "r"(b1));
}

// ---------------- setup: fold constants, build W^T (tf32) ----------------
__global__ void setup_kernel(const float* __restrict__ latent,
                             const float* __restrict__ weights,
                             const float* __restrict__ enc_w,
                             const float* __restrict__ enc_b,
                             const float* __restrict__ dec_w,
                             const float* __restrict__ dec_b) {
    int tid = threadIdx.x;
    // W[160 m][64 k] -> g_W[k*SW + m] (tf32-rounded)
    for (int i = tid; i < 160 * 64; i += 256) {
        int m = i >> 6, k = i & 63;
        float val;
        if (m < 32) {                       // folded scores1: A[c][ht]
            int h = m >> 2, t = m & 3;
            val = 0.f;
            for (int d = 0; d < 8; d++)
                val += latent[h * 32 + t * 8 + d]
                     * enc_w[(h * 16 + 2 * d) * 64 + k];
        } else if (m < 96) {                // v weights
            int hd = m - 32, h = hd >> 3, d = hd & 7;
            val = enc_w[(h * 16 + 2 * d + 1) * 64 + k];
        } else {                            // dec weights
            val = dec_w[(m - 96) * 64 + k];
        }
        g_W[k * SW + m] = to_tf32(val);
    }
    // biasAll[160]
    for (int i = tid; i < 160; i += 256) {
        float val;
        if (i < 32) {
            int h = i >> 2, t = i & 3;
            val = 0.f;
            for (int d = 0; d < 8; d++)
                val += latent[h * 32 + t * 8 + d] * enc_b[h * 16 + 2 * d];
        } else if (i < 96) {
            int hd = i - 32, h = hd >> 3, d = hd & 7;
            val = enc_b[h * 16 + 2 * d + 1];
        } else {
            val = dec_b[i - 96];
        }
        g_small[S_B + i] = val;
    }
    for (int i = tid; i < 1536; i += 256) {           // wt[m'][c]
        int m = i >> 6, c = i & 63;
        g_small[S_WT + i] = weights[c * 24 + m];
    }
    for (int i = tid; i < 256; i += 256) {            // q[hd][t]
        int hd = i >> 2, t = i & 3;
        int h = hd >> 3, d = hd & 7;
        g_small[S_Q + i] = latent[h * 32 + t * 8 + d];
    }
}

// ---------------- main fused kernel ----------------
__global__ void __launch_bounds__(NT, 2)
nsb_kernel(const float* __restrict__ x, float* __restrict__ out) {
    extern __shared__ float sm[];
    float* wy  = sm;                 // W^T during GEMM, Y afterwards
    float* xs  = sm + OFF_X;
    float* ss  = sm + OFF_SS;
    float* spb = sm + OFF_PB;

    const int tid = threadIdx.x;

    // W^T -> smem (float4 where possible)
    {
        const float4* src = (const float4*)g_W;
        float4* dst = (float4*)wy;
        for (int i = tid; i < W_F / 4; i += NT) dst[i] = src[i];
    }
    for (int i = tid; i < S_SZ; i += NT) ss[i] = g_small[i];

    // CTA -> (b, hp, wblk)
    const int cta  = blockIdx.x;
    const int wblk = cta % WBLK;
    const int hp   = (cta / WBLK) % HPn;
    const int b    = cta / (WBLK * HPn);

    // patchify: x -> X[n][k] (tf32-rounded), n = wl*9 + p0*3 + p1, k = c
    for (int i = tid; i < 64 * 3 * 24; i += NT) {
        int col = i % 24;
        int seg = i / 24;
        int p0  = seg % 3;
        int c   = seg / 3;
        int wl  = col / 3, p1 = col % 3;
        float v = x[((b * 64 + c) * Hn + hp * 3 + p0) * Wn + wblk * 24 + col];
        xs[(wl * 9 + p0 * 3 + p1) * SX + c] = to_tf32(v);
    }
    __syncthreads();

    const int warp = tid >> 5;
    const int lane = tid & 31;
    const int g = lane >> 2, t = lane & 3;

    // ================= GEMM: warp grid 2m x 4n =================
    const int mw = warp >> 2;            // 0,1 -> m rows [mw*80, mw*80+80)
    const int nw = warp & 3;
    const int m0 = mw * 80;
    int nb0, nb1, nb2, ntile;
    if (nw == 0) { nb0 = 0;  nb1 = 8;  nb2 = 16; ntile = 3; }
    else         { nb0 = 8 + nw * 16; nb1 = nb0 + 8; nb2 = 0; ntile = 2; }

    float acc[3][5][4];
#pragma unroll
    for (int ni = 0; ni < 3; ni++)
#pragma unroll
        for (int mi = 0; mi < 5; mi++)
#pragma unroll
            for (int j = 0; j < 4; j++) acc[ni][mi][j] = 0.f;

#pragma unroll 2
    for (int k0 = 0; k0 < 64; k0 += 8) {
        unsigned bf[3][2];
        bf[0][0] = __float_as_uint(xs[(nb0 + g) * SX + k0 + t]);
        bf[0][1] = __float_as_uint(xs[(nb0 + g) * SX + k0 + t + 4]);
        bf[1][0] = __float_as_uint(xs[(nb1 + g) * SX + k0 + t]);
        bf[1][1] = __float_as_uint(xs[(nb1 + g) * SX + k0 + t + 4]);
        if (ntile == 3) {
            bf[2][0] = __float_as_uint(xs[(nb2 + g) * SX + k0 + t]);
            bf[2][1] = __float_as_uint(xs[(nb2 + g) * SX + k0 + t + 4]);
        } else { bf[2][0] = 0u; bf[2][1] = 0u; }
#pragma unroll
        for (int mi = 0; mi < 5; mi++) {
            int mr = m0 + mi * 16;
            unsigned a0 = __float_as_uint(wy[(k0 + t) * SW + mr + g]);
            unsigned a1 = __float_as_uint(wy[(k0 + t) * SW + mr + g + 8]);
            unsigned a2 = __float_as_uint(wy[(k0 + t + 4) * SW + mr + g]);
            unsigned a3 = __float_as_uint(wy[(k0 + t + 4) * SW + mr + g + 8]);
            mma_tf32(acc[0][mi], a0, a1, a2, a3, bf[0][0], bf[0][1]);
            mma_tf32(acc[1][mi], a0, a1, a2, a3, bf[1][0], bf[1][1]);
            if (ntile == 3)
                mma_tf32(acc[2][mi], a0, a1, a2, a3, bf[2][0], bf[2][1]);
        }
    }
    __syncthreads();   // all warps done reading W -> region becomes Y

    // store C fragments + bias into Y[m][SY]
#pragma unroll
    for (int ni = 0; ni < 3; ni++) {
        if (ni >= ntile) break;
        int nbase = (ni == 0) ? nb0 : (ni == 1) ? nb1 : nb2;
#pragma unroll
        for (int mi = 0; mi < 5; mi++) {
            int r0 = m0 + mi * 16 + g;
            int r1 = r0 + 8;
            int cc = nbase + 2 * t;
            float b0 = ss[S_B + r0], b1 = ss[S_B + r1];
            wy[r0 * SY + cc]     = acc[ni][mi][0] + b0;
            wy[r0 * SY + cc + 1] = acc[ni][mi][1] + b0;
            wy[r1 * SY + cc]     = acc[ni][mi][2] + b1;
            wy[r1 * SY + cc + 1] = acc[ni][mi][3] + b1;
        }
    }
    __syncthreads();   // Y complete

    // ================= epilogue: warp = patch (R6 logic) =================
    const int pb = warp * 9;
    float* at = spb + warp * 320;   // attn1, overlaid with lp
    float* lp = at;

    // softmax over pos (lane = ht), s1 from Y rows [0,32)
    {
        float s1[9];
#pragma unroll
        for (int p = 0; p < 9; p++) s1[p] = wy[lane * SY + pb + p];
        float mx = s1[0];
#pragma unroll
        for (int p = 1; p < 9; p++) mx = fmaxf(mx, s1[p]);
        float sum = 0.f;
#pragma unroll
        for (int p = 0; p < 9; p++) { s1[p] = __expf(s1[p] - mx); sum += s1[p]; }
        float inv = 1.0f / sum;
#pragma unroll
        for (int p = 0; p < 9; p++) at[lane * 9 + p] = s1[p] * inv;
    }
    __syncwarp();

    // lt[h,t,d] = attn1 @ v + q ; v from Y rows [32,96)
    const int h0 = lane >> 3;
    float v0[9], v1[9];
#pragma unroll
    for (int p = 0; p < 9; p++) {
        v0[p] = wy[(32 + lane) * SY + pb + p];
        v1[p] = wy[(64 + lane) * SY + pb + p];
    }
    float lt0[4], lt1[4];
#pragma unroll
    for (int tt = 0; tt < 4; tt++) {
        float a0 = ss[S_Q + lane * 4 + tt];
        float a1 = ss[S_Q + (lane + 32) * 4 + tt];
        const float* r0 = at + (h0 * 4 + tt) * 9;
        const float* r1 = at + ((h0 + 4) * 4 + tt) * 9;
#pragma unroll
        for (int p = 0; p < 9; p++) {
            a0 = fmaf(r0[p], v0[p], a0);
            a1 = fmaf(r1[p], v1[p], a1);
        }
        lt0[tt] = a0; lt1[tt] = a1;
    }
    __syncwarp();   // attn1 fully read before lp overwrite

    // spectral basis mixing (angle-addition recurrence) -> lp[ch*5+t]
#pragma unroll
    for (int tt = 0; tt < 4; tt++) {
        float base0 = lt0[tt] * (float)(CUDART_PI / 12.0);
        float base1 = lt1[tt] * (float)(CUDART_PI / 12.0);
        float s0, c0, sB, cB;
        __sincosf(base0, &s0, &c0);
        __sincosf(base1, &sB, &cB);
        float acc0 = ss[S_WT + 12 * 64 + lane];       // m=0: sin=0, cos=1
        float acc1 = ss[S_WT + 12 * 64 + lane + 32];
        float sa = s0, ca = c0, sb = sB, cb = cB;
#pragma unroll
        for (int m = 1; m < 12; m++) {
            acc0 = fmaf(sa, ss[S_WT + m * 64 + lane],
                   fmaf(ca, ss[S_WT + (12 + m) * 64 + lane], acc0));
            acc1 = fmaf(sb, ss[S_WT + m * 64 + lane + 32],
                   fmaf(cb, ss[S_WT + (12 + m) * 64 + lane + 32], acc1));
            float ns = fmaf(sa, c0,  ca * s0);
            float nc = fmaf(ca, c0, -sa * s0);
            sa = ns; ca = nc;
            float ms = fmaf(sb, cB,  cb * sB);
            float mc = fmaf(cb, cB, -sb * sB);
            sb = ms; cb = mc;
        }
        lp[lane * 5 + tt]        = lt0[tt] + acc0;
        lp[(lane + 32) * 5 + tt] = lt1[tt] + acc1;
    }
    __syncwarp();

    // decoder attention (72 items = h x pos); xq in Y rows [96,160), in-place
    {
        float* xq = wy + 96 * SY + pb;
#pragma unroll
        for (int k = 0; k < 3; k++) {
            int item = lane + 32 * k;
            if (item < 72) {
                int h = item / 9, pos = item - h * 9;
                float sc[4] = {0.f, 0.f, 0.f, 0.f};
#pragma unroll
                for (int d = 0; d < 8; d++) {
                    float xv = xq[(h * 8 + d) * SY + pos];
                    const float* lr = lp + (h * 8 + d) * 5;
#pragma unroll
                    for (int tt = 0; tt < 4; tt++)
                        sc[tt] = fmaf(xv, lr[tt], sc[tt]);
                }
                float m2 = fmaxf(fmaxf(sc[0], sc[1]), fmaxf(sc[2], sc[3]));
                float es = 0.f;
#pragma unroll
                for (int tt = 0; tt < 4; tt++) {
                    sc[tt] = __expf(sc[tt] - m2); es += sc[tt];
                }
                float inv = 1.0f / es;
#pragma unroll
                for (int tt = 0; tt < 4; tt++) sc[tt] *= inv;
#pragma unroll
                for (int d = 0; d < 8; d++) {
                    const float* lr = lp + (h * 8 + d) * 5;
                    float o = 0.f;
#pragma unroll
                    for (int tt = 0; tt < 4; tt++)
                        o = fmaf(sc[tt], lr[tt], o);
                    xq[(h * 8 + d) * SY + pos] = o;
                }
            }
        }
    }
    __syncthreads();

    // un-patchify store; residual re-read from global x (exact fp32)
    for (int i = tid; i < 64 * 3 * 24; i += NT) {
        int col = i % 24;
        int seg = i / 24;
        int p0  = seg % 3;
        int c   = seg / 3;
        int wl  = col / 3, p1 = col % 3;
        int pos = p0 * 3 + p1;
        size_t gidx = ((size_t)(b * 64 + c) * Hn + hp * 3 + p0) * Wn
                      + wblk * 24 + col;
        out[gidx] = wy[(96 + c) * SY + wl * 9 + pos] + __ldg(x + gidx);
    }
}

extern "C" void kernel_launch(void* const* d_in, const int* in_sizes, int n_in,
                              void* d_out, int out_size) {
    const float* x       = (const float*)d_in[0];
    const float* latent  = (const float*)d_in[1];
    const float* weights = (const float*)d_in[2];
    const float* enc_w   = (const float*)d_in[3];
    const float* enc_b   = (const float*)d_in[4];
    const float* dec_w   = (const float*)d_in[5];
    const float* dec_b   = (const float*)d_in[6];
    float* out = (float*)d_out;

    cudaFuncSetAttribute(nsb_kernel,
                         cudaFuncAttributeMaxDynamicSharedMemorySize, SMEM_B);

    setup_kernel<<<1, 256>>>(latent, weights, enc_w, enc_b, dec_w, dec_b);
    nsb_kernel<<<GRID, NT, SMEM_B>>>(x, out);
}

// round 11
// speedup vs baseline: 1.3048x; 1.3048x over previous
#include <cuda_runtime.h>
#include <math_constants.h>

// ---------------------------------------------------------------------------
// NeuralSpectralBlock2D  (B=16, C=64, H=W=240, P=3, HEAD=8, dh=8, T=4, M=12)
// tf32 tensor-core GEMM per CTA:  Y[160 x 72] = W[160 x 64] * X[64 x 72]
// (rows 0-31 scores1-folded, 32-95 v, 96-159 xq; bias in Y-store epilogue).
// NT=512 (16 warps), 2 CTAs/SM = 32 warps/SM, <=64 regs.
// GEMM: 15-warp 5m x 3n grid, conflict-free frags (SW=168, SX=68).
// Epilogue split 2 warps/patch. Y overlays W; at/lp overlay X.
// ---------------------------------------------------------------------------

#define Bn    16
#define Cn    64
#define Hn    240
#define Wn    240
#define NP    8
#define NT    512

#define HPn   80
#define WPn   80
#define WBLK  (WPn / NP)          // 10
#define GRID  (Bn * HPn * WBLK)   // 12800

#define SW 168            // W^T stride: bank = 8t+g -> conflict-free
#define SX 68             // X stride:   bank = 4g+t -> conflict-free
#define SY 73             // Y stride:   lane*9 mod 32 -> conflict-free reads

#define W_F   (64 * SW)           // 10752
#define Y_F   (160 * SY)          // 11680
#define X_F   (72 * SX)           // 4896

// small consts
#define S_B   0                   // biasAll[160]
#define S_WT  160                 // wt[m'][c] 1536
#define S_Q   1696                // q[hd][t]  256
#define S_SZ  1952

#define OFF_X   Y_F               // X during GEMM; at/lp (8x320) after
#define OFF_SS  (OFF_X + X_F)
#define SMEM_F  (OFF_SS + S_SZ)       // 18528 floats
#define SMEM_B  (SMEM_F * 4)          // 74112 bytes

__device__ __align__(16) float g_W[W_F];
__device__ __align__(16) float g_small[S_SZ];

__device__ __forceinline__ float to_tf32(float v) {
    unsigned o;
    asm("cvt.rna.tf32.f32 %0, %1;" : "=r"(o) : "f"(v));
    return __uint_as_float(o);
}

__device__ __forceinline__ void mma_tf32(float c[4],
                                         unsigned a0, unsigned a1,
                                         unsigned a2, unsigned a3,
                                         unsigned b0, unsigned b1) {
    asm volatile(
        "mma.sync.aligned.m16n8k8.row.col.f32.tf32.tf32.f32 "
        "{%0,%1,%2,%3}, {%4,%5,%6,%7}, {%8,%9}, {%0,%1,%2,%3};\n"
        : "+f"(c[0]), "+f"(c[1]), "+f"(c[2]), "+f"(c[3])
        : "r"(a0), "r"(a1), "r"(a2), "r"(a3), "r"(b0), "r"(b1));
}

// ---------------- setup: fold constants, build W^T (tf32) ----------------
__global__ void setup_kernel(const float* __restrict__ latent,
                             const float* __restrict__ weights,
                             const float* __restrict__ enc_w,
                             const float* __restrict__ enc_b,
                             const float* __restrict__ dec_w,
                             const float* __restrict__ dec_b) {
    int tid = threadIdx.x;
    for (int i = tid; i < 160 * 64; i += 256) {
        int m = i >> 6, k = i & 63;
        float val;
        if (m < 32) {                       // folded scores1: A[c][ht]
            int h = m >> 2, t = m & 3;
            val = 0.f;
            for (int d = 0; d < 8; d++)
                val += latent[h * 32 + t * 8 + d]
                     * enc_w[(h * 16 + 2 * d) * 64 + k];
        } else if (m < 96) {                // v weights
            int hd = m - 32, h = hd >> 3, d = hd & 7;
            val = enc_w[(h * 16 + 2 * d + 1) * 64 + k];
        } else {                            // dec weights
            val = dec_w[(m - 96) * 64 + k];
        }
        g_W[k * SW + m] = to_tf32(val);
    }
    for (int i = tid; i < 160; i += 256) {
        float val;
        if (i < 32) {
            int h = i >> 2, t = i & 3;
            val = 0.f;
            for (int d = 0; d < 8; d++)
                val += latent[h * 32 + t * 8 + d] * enc_b[h * 16 + 2 * d];
        } else if (i < 96) {
            int hd = i - 32, h = hd >> 3, d = hd & 7;
            val = enc_b[h * 16 + 2 * d + 1];
        } else {
            val = dec_b[i - 96];
        }
        g_small[S_B + i] = val;
    }
    for (int i = tid; i < 1536; i += 256) {
        int m = i >> 6, c = i & 63;
        g_small[S_WT + i] = weights[c * 24 + m];
    }
    for (int i = tid; i < 256; i += 256) {
        int hd = i >> 2, t = i & 3;
        int h = hd >> 3, d = hd & 7;
        g_small[S_Q + i] = latent[h * 32 + t * 8 + d];
    }
}

// ---------------- main fused kernel ----------------
__global__ void __launch_bounds__(NT, 2)
nsb_kernel(const float* __restrict__ x, float* __restrict__ out) {
    extern __shared__ float sm[];
    float* wy  = sm;                 // W^T during GEMM, Y afterwards
    float* xs  = sm + OFF_X;         // X during GEMM; at/lp after
    float* ss  = sm + OFF_SS;
    float* spb = xs;                 // per-patch at/lp (overlay)

    const int tid = threadIdx.x;

    // W^T -> smem
    {
        const float4* src = (const float4*)g_W;
        float4* dst = (float4*)wy;
        for (int i = tid; i < W_F / 4; i += NT) dst[i] = src[i];
    }
    for (int i = tid; i < S_SZ; i += NT) ss[i] = g_small[i];

    const int cta  = blockIdx.x;
    const int wblk = cta % WBLK;
    const int hp   = (cta / WBLK) % HPn;
    const int b    = cta / (WBLK * HPn);

    // patchify: x -> X[n][k] (tf32), n = wl*9 + p0*3 + p1, k = c
    for (int i = tid; i < 64 * 3 * 24; i += NT) {
        int col = i % 24;
        int seg = i / 24;
        int p0  = seg % 3;
        int c   = seg / 3;
        int wl  = col / 3, p1 = col % 3;
        float v = x[((b * 64 + c) * Hn + hp * 3 + p0) * Wn + wblk * 24 + col];
        xs[(wl * 9 + p0 * 3 + p1) * SX + c] = to_tf32(v);
    }
    __syncthreads();

    const int warp = tid >> 5;
    const int lane = tid & 31;
    const int g = lane >> 2, t = lane & 3;

    // ================= GEMM: 15-warp grid 5m x 3n =================
    float acc[2][3][4];
    const int wm = warp / 3, wn = warp - wm * 3;     // wm<5 when warp<15
    const int m0 = wm * 32, n0 = wn * 24;
    if (warp < 15) {
#pragma unroll
        for (int mt = 0; mt < 2; mt++)
#pragma unroll
            for (int nt = 0; nt < 3; nt++)
#pragma unroll
                for (int j = 0; j < 4; j++) acc[mt][nt][j] = 0.f;
#pragma unroll 2
        for (int k0 = 0; k0 < 64; k0 += 8) {
            unsigned bf[3][2];
#pragma unroll
            for (int nt = 0; nt < 3; nt++) {
                bf[nt][0] = __float_as_uint(xs[(n0 + nt * 8 + g) * SX + k0 + t]);
                bf[nt][1] = __float_as_uint(xs[(n0 + nt * 8 + g) * SX + k0 + t + 4]);
            }
#pragma unroll
            for (int mt = 0; mt < 2; mt++) {
                int mr = m0 + mt * 16;
                unsigned a0 = __float_as_uint(wy[(k0 + t) * SW + mr + g]);
                unsigned a1 = __float_as_uint(wy[(k0 + t) * SW + mr + g + 8]);
                unsigned a2 = __float_as_uint(wy[(k0 + t + 4) * SW + mr + g]);
                unsigned a3 = __float_as_uint(wy[(k0 + t + 4) * SW + mr + g + 8]);
#pragma unroll
                for (int nt = 0; nt < 3; nt++)
                    mma_tf32(acc[mt][nt], a0, a1, a2, a3, bf[nt][0], bf[nt][1]);
            }
        }
    }
    __syncthreads();   // all GEMM reads of W done -> region becomes Y

    if (warp < 15) {
#pragma unroll
        for (int mt = 0; mt < 2; mt++) {
            int r0 = m0 + mt * 16 + g;
            int r1 = r0 + 8;
            float b0 = ss[S_B + r0], b1 = ss[S_B + r1];
#pragma unroll
            for (int nt = 0; nt < 3; nt++) {
                int cc = n0 + nt * 8 + 2 * t;
                wy[r0 * SY + cc]     = acc[mt][nt][0] + b0;
                wy[r0 * SY + cc + 1] = acc[mt][nt][1] + b0;
                wy[r1 * SY + cc]     = acc[mt][nt][2] + b1;
                wy[r1 * SY + cc + 1] = acc[mt][nt][3] + b1;
            }
        }
    }
    __syncthreads();   // Y complete; X dead -> spb live

    // ===== P1: softmax (warps 0-7, warp = patch; lane = ht) =====
    if (warp < 8) {
        float* at = spb + warp * 320;
        float s1[9];
#pragma unroll
        for (int p = 0; p < 9; p++) s1[p] = wy[lane * SY + warp * 9 + p];
        float mx = s1[0];
#pragma unroll
        for (int p = 1; p < 9; p++) mx = fmaxf(mx, s1[p]);
        float sum = 0.f;
#pragma unroll
        for (int p = 0; p < 9; p++) { s1[p] = __expf(s1[p] - mx); sum += s1[p]; }
        float inv = 1.0f / sum;
#pragma unroll
        for (int p = 0; p < 9; p++) at[lane * 9 + p] = s1[p] * inv;
    }
    __syncthreads();

    // ===== P2: lt + spectral, 2 warps/patch (channel halves) =====
    const int patch = warp & 7;
    const int half  = warp >> 3;
    const int ch    = lane + (half << 5);
    float* at = spb + patch * 320;
    float* lp = at;

    float lt[4];
    {
        float v[9];
#pragma unroll
        for (int p = 0; p < 9; p++)
            v[p] = wy[(32 + ch) * SY + patch * 9 + p];
        const int hh = ch >> 3;
#pragma unroll
        for (int tt = 0; tt < 4; tt++) {
            float a = ss[S_Q + ch * 4 + tt];
            const float* r = at + (hh * 4 + tt) * 9;
#pragma unroll
            for (int p = 0; p < 9; p++) a = fmaf(r[p], v[p], a);
            lt[tt] = a;
        }
    }
    __syncthreads();   // everyone done reading attn1 before lp overwrite

#pragma unroll
    for (int tt = 0; tt < 4; tt++) {
        float base = lt[tt] * (float)(CUDART_PI / 12.0);
        float s0, c0;
        __sincosf(base, &s0, &c0);
        float acc0 = ss[S_WT + 12 * 64 + ch];          // m=0: sin=0, cos=1
        float sa = s0, ca = c0;
#pragma unroll
        for (int m = 1; m < 12; m++) {
            acc0 = fmaf(sa, ss[S_WT + m * 64 + ch],
                   fmaf(ca, ss[S_WT + (12 + m) * 64 + ch], acc0));
            float ns = fmaf(sa, c0,  ca * s0);
            float nc = fmaf(ca, c0, -sa * s0);
            sa = ns; ca = nc;
        }
        lp[ch * 5 + tt] = lt[tt] + acc0;
    }
    __syncthreads();   // lp complete

    // ===== P3: decoder attention, 2 warps/patch (item halves) =====
    {
        float* xq = wy + 96 * SY + patch * 9;
#pragma unroll
        for (int k = 0; k < 2; k++) {
            int item = half * 36 + k * 32 + lane;
            if (k == 0 || lane < 4) {
                int h = item / 9, pos = item - h * 9;
                float sc[4] = {0.f, 0.f, 0.f, 0.f};
#pragma unroll
                for (int d = 0; d < 8; d++) {
                    float xv = xq[(h * 8 + d) * SY + pos];
                    const float* lr = lp + (h * 8 + d) * 5;
#pragma unroll
                    for (int tt = 0; tt < 4; tt++)
                        sc[tt] = fmaf(xv, lr[tt], sc[tt]);
                }
                float m2 = fmaxf(fmaxf(sc[0], sc[1]), fmaxf(sc[2], sc[3]));
                float es = 0.f;
#pragma unroll
                for (int tt = 0; tt < 4; tt++) {
                    sc[tt] = __expf(sc[tt] - m2); es += sc[tt];
                }
                float inv = 1.0f / es;
#pragma unroll
                for (int tt = 0; tt < 4; tt++) sc[tt] *= inv;
#pragma unroll
                for (int d = 0; d < 8; d++) {
                    const float* lr = lp + (h * 8 + d) * 5;
                    float o = 0.f;
#pragma unroll
                    for (int tt = 0; tt < 4; tt++)
                        o = fmaf(sc[tt], lr[tt], o);
                    xq[(h * 8 + d) * SY + pos] = o;
                }
            }
        }
    }
    __syncthreads();

    // un-patchify store; residual re-read from global x (exact fp32)
    for (int i = tid; i < 64 * 3 * 24; i += NT) {
        int col = i % 24;
        int seg = i / 24;
        int p0  = seg % 3;
        int c   = seg / 3;
        int wl  = col / 3, p1 = col % 3;
        int pos = p0 * 3 + p1;
        size_t gidx = ((size_t)(b * 64 + c) * Hn + hp * 3 + p0) * Wn
                      + wblk * 24 + col;
        out[gidx] = wy[(96 + c) * SY + wl * 9 + pos] + __ldg(x + gidx);
    }
}

extern "C" void kernel_launch(void* const* d_in, const int* in_sizes, int n_in,
                              void* d_out, int out_size) {
    const float* x       = (const float*)d_in[0];
    const float* latent  = (const float*)d_in[1];
    const float* weights = (const float*)d_in[2];
    const float* enc_w   = (const float*)d_in[3];
    const float* enc_b   = (const float*)d_in[4];
    const float* dec_w   = (const float*)d_in[5];
    const float* dec_b   = (const float*)d_in[6];
    float* out = (float*)d_out;

    cudaFuncSetAttribute(nsb_kernel,
                         cudaFuncAttributeMaxDynamicSharedMemorySize, SMEM_B);

    setup_kernel<<<1, 256>>>(latent, weights, enc_w, enc_b, dec_w, dec_b);
    nsb_kernel<<<GRID, NT, SMEM_B>>>(x, out);
}

// round 12
// speedup vs baseline: 1.9161x; 1.4685x over previous
#include <cuda_runtime.h>
#include <math_constants.h>

// ---------------------------------------------------------------------------
// NeuralSpectralBlock2D  (B=16, C=64, H=W=240, P=3, HEAD=8, dh=8, T=4, M=12)
// tf32 tensor-core GEMM per CTA:  Y[160 x 72] = W[160 x 64] * X[64 x 72]
// NT=512, 2 CTAs/SM. R12: instruction diet — float4 patchify/unpatchify,
// Chebyshev spectral recurrence (m-outer), no cvt on X (HW tf32 truncation).
// ---------------------------------------------------------------------------

#define Bn    16
#define Cn    64
#define Hn    240
#define Wn    240
#define NP    8
#define NT    512

#define HPn   80
#define WPn   80
#define WBLK  (WPn / NP)          // 10
#define GRID  (Bn * HPn * WBLK)   // 12800

#define SW  168           // W^T stride: bank = 8t+g -> conflict-free
#define SXK 72            // X stride (k-major): 72 mod 32 = 8 -> conflict-free
#define SY  73            // Y stride

#define W_F   (64 * SW)           // 10752
#define Y_F   (160 * SY)          // 11680
#define X_F   (64 * SXK)          // 4608

// small consts
#define S_B   0                   // biasAll[160]
#define S_WT  160                 // wt[m'][c] 1536
#define S_Q   1696                // q[hd][t]  256
#define S_SZ  1952

#define OFF_X   Y_F               // X during GEMM; at/lp (8x320=2560) after
#define OFF_SS  (OFF_X + X_F)
#define SMEM_F  (OFF_SS + S_SZ)       // 18240 floats
#define SMEM_B  (SMEM_F * 4)          // 72960 bytes

__device__ __align__(16) float g_W[W_F];
__device__ __align__(16) float g_small[S_SZ];

__device__ __forceinline__ float to_tf32(float v) {
    unsigned o;
    asm("cvt.rna.tf32.f32 %0, %1;" : "=r"(o) : "f"(v));
    return __uint_as_float(o);
}

__device__ __forceinline__ void mma_tf32(float c[4],
                                         unsigned a0, unsigned a1,
                                         unsigned a2, unsigned a3,
                                         unsigned b0, unsigned b1) {
    asm volatile(
        "mma.sync.aligned.m16n8k8.row.col.f32.tf32.tf32.f32 "
        "{%0,%1,%2,%3}, {%4,%5,%6,%7}, {%8,%9}, {%0,%1,%2,%3};\n"
        : "+f"(c[0]), "+f"(c[1]), "+f"(c[2]), "+f"(c[3])
        : "r"(a0), "r"(a1), "r"(a2), "r"(a3), "r"(b0), "r"(b1));
}

// ---------------- setup: fold constants, build W^T (tf32) ----------------
__global__ void setup_kernel(const float* __restrict__ latent,
                             const float* __restrict__ weights,
                             const float* __restrict__ enc_w,
                             const float* __restrict__ enc_b,
                             const float* __restrict__ dec_w,
                             const float* __restrict__ dec_b) {
    int tid = threadIdx.x;
    for (int i = tid; i < 160 * 64; i += 256) {
        int m = i >> 6, k = i & 63;
        float val;
        if (m < 32) {                       // folded scores1: A[c][ht]
            int h = m >> 2, t = m & 3;
            val = 0.f;
            for (int d = 0; d < 8; d++)
                val += latent[h * 32 + t * 8 + d]
                     * enc_w[(h * 16 + 2 * d) * 64 + k];
        } else if (m < 96) {                // v weights
            int hd = m - 32, h = hd >> 3, d = hd & 7;
            val = enc_w[(h * 16 + 2 * d + 1) * 64 + k];
        } else {                            // dec weights
            val = dec_w[(m - 96) * 64 + k];
        }
        g_W[k * SW + m] = to_tf32(val);
    }
    for (int i = tid; i < 160; i += 256) {
        float val;
        if (i < 32) {
            int h = i >> 2, t = i & 3;
            val = 0.f;
            for (int d = 0; d < 8; d++)
                val += latent[h * 32 + t * 8 + d] * enc_b[h * 16 + 2 * d];
        } else if (i < 96) {
            int hd = i - 32, h = hd >> 3, d = hd & 7;
            val = enc_b[h * 16 + 2 * d + 1];
        } else {
            val = dec_b[i - 96];
        }
        g_small[S_B + i] = val;
    }
    for (int i = tid; i < 1536; i += 256) {
        int m = i >> 6, c = i & 63;
        g_small[S_WT + i] = weights[c * 24 + m];
    }
    for (int i = tid; i < 256; i += 256) {
        int hd = i >> 2, t = i & 3;
        int h = hd >> 3, d = hd & 7;
        g_small[S_Q + i] = latent[h * 32 + t * 8 + d];
    }
}

// ---------------- main fused kernel ----------------
__global__ void __launch_bounds__(NT, 2)
nsb_kernel(const float* __restrict__ x, float* __restrict__ out) {
    extern __shared__ float sm[];
    float* wy  = sm;                 // W^T during GEMM, Y afterwards
    float* xs  = sm + OFF_X;         // X (k-major) during GEMM; at/lp after
    float* ss  = sm + OFF_SS;
    float* spb = xs;                 // per-patch at/lp (overlay)

    const int tid = threadIdx.x;

    // W^T -> smem
    {
        const float4* src = (const float4*)g_W;
        float4* dst = (float4*)wy;
        for (int i = tid; i < W_F / 4; i += NT) dst[i] = src[i];
    }
    for (int i = tid; i < S_SZ; i += NT) ss[i] = g_small[i];

    const int cta  = blockIdx.x;
    const int wblk = cta % WBLK;
    const int hp   = (cta / WBLK) % HPn;
    const int b    = cta / (WBLK * HPn);

    // patchify: float4 loads; X[k][n] k-major (raw fp32; HW truncates to tf32)
    for (int i = tid; i < 1152; i += NT) {
        int c  = i / 18;
        int r  = i - c * 18;
        int p0 = r / 6;
        int q  = r - p0 * 6;
        float4 v = *(const float4*)(x + ((size_t)(b * 64 + c) * Hn
                                         + hp * 3 + p0) * Wn + wblk * 24 + 4 * q);
#pragma unroll
        for (int j = 0; j < 4; j++) {
            int col = 4 * q + j;
            int wl = col / 3, p1 = col - wl * 3;
            xs[c * SXK + wl * 9 + p0 * 3 + p1] = ((const float*)&v)[j];
        }
    }
    __syncthreads();

    const int warp = tid >> 5;
    const int lane = tid & 31;
    const int g = lane >> 2, t = lane & 3;

    // ================= GEMM: 15-warp grid 5m x 3n =================
    float acc[2][3][4];
    const int wm = warp / 3, wn = warp - wm * 3;
    const int m0 = wm * 32, n0 = wn * 24;
    if (warp < 15) {
#pragma unroll
        for (int mt = 0; mt < 2; mt++)
#pragma unroll
            for (int nt = 0; nt < 3; nt++)
#pragma unroll
                for (int j = 0; j < 4; j++) acc[mt][nt][j] = 0.f;
#pragma unroll 2
        for (int k0 = 0; k0 < 64; k0 += 8) {
            unsigned bf[3][2];
#pragma unroll
            for (int nt = 0; nt < 3; nt++) {
                bf[nt][0] = __float_as_uint(xs[(k0 + t) * SXK + n0 + nt * 8 + g]);
                bf[nt][1] = __float_as_uint(xs[(k0 + t + 4) * SXK + n0 + nt * 8 + g]);
            }
#pragma unroll
            for (int mt = 0; mt < 2; mt++) {
                int mr = m0 + mt * 16;
                unsigned a0 = __float_as_uint(wy[(k0 + t) * SW + mr + g]);
                unsigned a1 = __float_as_uint(wy[(k0 + t) * SW + mr + g + 8]);
                unsigned a2 = __float_as_uint(wy[(k0 + t + 4) * SW + mr + g]);
                unsigned a3 = __float_as_uint(wy[(k0 + t + 4) * SW + mr + g + 8]);
#pragma unroll
                for (int nt = 0; nt < 3; nt++)
                    mma_tf32(acc[mt][nt], a0, a1, a2, a3, bf[nt][0], bf[nt][1]);
            }
        }
    }
    __syncthreads();   // all GEMM reads of W/X done -> wy becomes Y, xs free

    if (warp < 15) {
#pragma unroll
        for (int mt = 0; mt < 2; mt++) {
            int r0 = m0 + mt * 16 + g;
            int r1 = r0 + 8;
            float b0 = ss[S_B + r0], b1 = ss[S_B + r1];
#pragma unroll
            for (int nt = 0; nt < 3; nt++) {
                int cc = n0 + nt * 8 + 2 * t;
                wy[r0 * SY + cc]     = acc[mt][nt][0] + b0;
                wy[r0 * SY + cc + 1] = acc[mt][nt][1] + b0;
                wy[r1 * SY + cc]     = acc[mt][nt][2] + b1;
                wy[r1 * SY + cc + 1] = acc[mt][nt][3] + b1;
            }
        }
    }
    __syncthreads();   // Y complete

    // ===== P1: softmax (warps 0-7, warp = patch; lane = ht) =====
    if (warp < 8) {
        float* at = spb + warp * 320;
        float s1[9];
#pragma unroll
        for (int p = 0; p < 9; p++) s1[p] = wy[lane * SY + warp * 9 + p];
        float mx = s1[0];
#pragma unroll
        for (int p = 1; p < 9; p++) mx = fmaxf(mx, s1[p]);
        float sum = 0.f;
#pragma unroll
        for (int p = 0; p < 9; p++) { s1[p] = __expf(s1[p] - mx); sum += s1[p]; }
        float inv = 1.0f / sum;
#pragma unroll
        for (int p = 0; p < 9; p++) at[lane * 9 + p] = s1[p] * inv;
    }
    __syncthreads();

    // ===== P2: lt + spectral, 2 warps/patch (channel halves) =====
    const int patch = warp & 7;
    const int half  = warp >> 3;
    const int ch    = lane + (half << 5);
    float* at = spb + patch * 320;
    float* lp = at;

    float lt[4];
    {
        float v[9];
#pragma unroll
        for (int p = 0; p < 9; p++)
            v[p] = wy[(32 + ch) * SY + patch * 9 + p];
        const int hh = ch >> 3;
#pragma unroll
        for (int tt = 0; tt < 4; tt++) {
            float a = ss[S_Q + ch * 4 + tt];
            const float* r = at + (hh * 4 + tt) * 9;
#pragma unroll
            for (int p = 0; p < 9; p++) a = fmaf(r[p], v[p], a);
            lt[tt] = a;
        }
    }
    __syncthreads();   // all reads of attn1 done before lp overwrite

    // spectral: Chebyshev recurrence, m-outer (2 LDS per m)
    {
        float c2[4], scur[4], ccur[4], sprev[4], cprev[4], acc0[4];
        float w0c = ss[S_WT + 12 * 64 + ch];           // m=0: sin=0, cos=1
#pragma unroll
        for (int tt = 0; tt < 4; tt++) {
            float base = lt[tt] * (float)(CUDART_PI / 12.0);
            float s0, c0;
            __sincosf(base, &s0, &c0);
            c2[tt] = 2.0f * c0;
            scur[tt] = s0; ccur[tt] = c0;
            sprev[tt] = 0.f; cprev[tt] = 1.f;
            acc0[tt] = w0c;
        }
#pragma unroll
        for (int m = 1; m < 12; m++) {
            float ws = ss[S_WT + m * 64 + ch];
            float wc = ss[S_WT + (12 + m) * 64 + ch];
#pragma unroll
            for (int tt = 0; tt < 4; tt++) {
                acc0[tt] = fmaf(scur[tt], ws, fmaf(ccur[tt], wc, acc0[tt]));
                float sn = fmaf(c2[tt], scur[tt], -sprev[tt]);
                float cn = fmaf(c2[tt], ccur[tt], -cprev[tt]);
                sprev[tt] = scur[tt]; cprev[tt] = ccur[tt];
                scur[tt] = sn; ccur[tt] = cn;
            }
        }
#pragma unroll
        for (int tt = 0; tt < 4; tt++)
            lp[ch * 5 + tt] = lt[tt] + acc0[tt];
    }
    __syncthreads();   // lp complete

    // ===== P3: decoder attention, 2 warps/patch (item halves) =====
    {
        float* xq = wy + 96 * SY + patch * 9;
#pragma unroll
        for (int k = 0; k < 2; k++) {
            int item = half * 36 + k * 32 + lane;
            if (k == 0 || lane < 4) {
                int h = item / 9, pos = item - h * 9;
                float sc[4] = {0.f, 0.f, 0.f, 0.f};
#pragma unroll
                for (int d = 0; d < 8; d++) {
                    float xv = xq[(h * 8 + d) * SY + pos];
                    const float* lr = lp + (h * 8 + d) * 5;
#pragma unroll
                    for (int tt = 0; tt < 4; tt++)
                        sc[tt] = fmaf(xv, lr[tt], sc[tt]);
                }
                float m2 = fmaxf(fmaxf(sc[0], sc[1]), fmaxf(sc[2], sc[3]));
                float es = 0.f;
#pragma unroll
                for (int tt = 0; tt < 4; tt++) {
                    sc[tt] = __expf(sc[tt] - m2); es += sc[tt];
                }
                float inv = 1.0f / es;
#pragma unroll
                for (int tt = 0; tt < 4; tt++) sc[tt] *= inv;
#pragma unroll
                for (int d = 0; d < 8; d++) {
                    const float* lr = lp + (h * 8 + d) * 5;
                    float o = 0.f;
#pragma unroll
                    for (int tt = 0; tt < 4; tt++)
                        o = fmaf(sc[tt], lr[tt], o);
                    xq[(h * 8 + d) * SY + pos] = o;
                }
            }
        }
    }
    __syncthreads();

    // un-patchify: float4 residual read + float4 store
    for (int i = tid; i < 1152; i += NT) {
        int c  = i / 18;
        int r  = i - c * 18;
        int p0 = r / 6;
        int q  = r - p0 * 6;
        size_t gbase = ((size_t)(b * 64 + c) * Hn + hp * 3 + p0) * Wn
                       + wblk * 24 + 4 * q;
        float4 rx = *(const float4*)(x + gbase);
        float4 o;
#pragma unroll
        for (int j = 0; j < 4; j++) {
            int col = 4 * q + j;
            int wl = col / 3, p1 = col - wl * 3;
            ((float*)&o)[j] = wy[(96 + c) * SY + wl * 9 + p0 * 3 + p1]
                              + ((const float*)&rx)[j];
        }
        *(float4*)(out + gbase) = o;
    }
}

extern "C" void kernel_launch(void* const* d_in, const int* in_sizes, int n_in,
                              void* d_out, int out_size) {
    const float* x       = (const float*)d_in[0];
    const float* latent  = (const float*)d_in[1];
    const float* weights = (const float*)d_in[2];
    const float* enc_w   = (const float*)d_in[3];
    const float* enc_b   = (const float*)d_in[4];
    const float* dec_w   = (const float*)d_in[5];
    const float* dec_b   = (const float*)d_in[6];
    float* out = (float*)d_out;

    cudaFuncSetAttribute(nsb_kernel,
                         cudaFuncAttributeMaxDynamicSharedMemorySize, SMEM_B);

    setup_kernel<<<1, 256>>>(latent, weights, enc_w, enc_b, dec_w, dec_b);
    nsb_kernel<<<GRID, NT, SMEM_B>>>(x, out);
}